// round 11
// baseline (speedup 1.0000x reference)
#include <cuda_runtime.h>
#include <cuda_fp16.h>
#include <cstdint>

// Problem constants (fixed by the dataset)
#define NN 100000
#define NE 1600000
#define DD 64
#define CAP 64          // bucket capacity per node (Poisson(16): P(deg>64)~2e-22)

#define XS_STRIDE 72    // halves; 144B rows: 16B-aligned + conflict-free ldmatrix

// ---------------- device scratch (no allocations allowed) ----------------
// g_cnt relies on BSS zero-init; agg layer-2 re-zeroes it (replay invariant).
__device__ __align__(256) int     g_cnt[NN];
__device__ __align__(256) float   g_dinv[NN];
__device__ __align__(256) int     g_bkt[(size_t)NN * CAP];   // bucket CSR
__device__ __align__(256) __half2 g_hn[(size_t)NN * 32];     // x@W (UNSCALED), fp16
__device__ __align__(256) __half  g_h1h[(size_t)NN * DD];    // layer-1 out, fp16

// -------- GEMM (+ tail-fused edge scatter on layer 0) ----------------------
// Block = 256 threads/8 warps/256 rows. mma.sync.m16n8k16 f32.f16.f16.f32.
// Scatter runs AFTER the epilogue: block i's atomics overlap blocks i+1..'s
// staging/MMA across waves (R10 put it before the barrier -> zero overlap).
__global__ void __launch_bounds__(256) k_gemm(
    const float* __restrict__ emb, const float* __restrict__ W,
    const int* __restrict__ src, const int* __restrict__ dst,
    int e2, int layer, int n) {
    __shared__ __half xs[256 * XS_STRIDE];       // 36864 B
    __shared__ __half wt[64 * XS_STRIDE];        //  9216 B  (wt[n][k])
    int tid = threadIdx.x;
    int base = blockIdx.x * 256;

    // ---- stage x rows -> fp16 shared ----
    if (layer == 0) {
        int row = base + tid;
        const float4* xr = reinterpret_cast<const float4*>(emb + (size_t)row * DD);
        bool v = row < n;
        __half2* dstp = reinterpret_cast<__half2*>(&xs[tid * XS_STRIDE]);
#pragma unroll
        for (int kk = 0; kk < 16; kk++) {
            float4 q = v ? xr[kk] : make_float4(0.f, 0.f, 0.f, 0.f);
            dstp[kk * 2]     = __floats2half2_rn(q.x, q.y);
            dstp[kk * 2 + 1] = __floats2half2_rn(q.z, q.w);
        }
    } else {
        const uint4* inp = reinterpret_cast<const uint4*>(g_h1h);
        uint4 z = make_uint4(0, 0, 0, 0);
#pragma unroll
        for (int ii = 0; ii < 8; ii++) {
            int i = tid + 256 * ii;
            int r = i >> 3, pc = i & 7;
            int gr = base + r;
            uint4 v = (gr < n) ? inp[(size_t)gr * 8 + pc] : z;
            reinterpret_cast<uint4*>(&xs[r * XS_STRIDE])[pc] = v;
        }
    }
    // ---- stage W -> fp16 transposed shared (wt[n][k]) ----
    {
        const float4* Wp4 = reinterpret_cast<const float4*>(W);
#pragma unroll
        for (int ii = 0; ii < 4; ii++) {
            int i4 = tid + 256 * ii;             // 1024 float4 total
            float4 wv = Wp4[i4];
            int flat = i4 * 4;
            int k = flat >> 6;
            int nn = flat & 63;
            wt[(nn)     * XS_STRIDE + k] = __float2half_rn(wv.x);
            wt[(nn + 1) * XS_STRIDE + k] = __float2half_rn(wv.y);
            wt[(nn + 2) * XS_STRIDE + k] = __float2half_rn(wv.z);
            wt[(nn + 3) * XS_STRIDE + k] = __float2half_rn(wv.w);
        }
    }
    __syncthreads();

    int wid = tid >> 5, lane = tid & 31;
    int g = lane >> 2, t = lane & 3;
    uint32_t xs_u32 = (uint32_t)__cvta_generic_to_shared(xs);

    // A fragments via ldmatrix.x4
    uint32_t afr[2][4][4];
#pragma unroll
    for (int mt = 0; mt < 2; mt++) {
        int rsh = wid * 32 + mt * 16 + (lane & 15);
#pragma unroll
        for (int kc = 0; kc < 4; kc++) {
            uint32_t addr = xs_u32 + rsh * (XS_STRIDE * 2) + kc * 32 + (lane >> 4) * 16;
            asm volatile("ldmatrix.sync.aligned.m8n8.x4.shared.b16 {%0,%1,%2,%3}, [%4];"
                         : "=r"(afr[mt][kc][0]), "=r"(afr[mt][kc][1]),
                           "=r"(afr[mt][kc][2]), "=r"(afr[mt][kc][3])
                         : "r"(addr));
        }
    }

    float c[8][2][4];
#pragma unroll
    for (int nt = 0; nt < 8; nt++)
#pragma unroll
        for (int mt = 0; mt < 2; mt++)
#pragma unroll
            for (int q = 0; q < 4; q++) c[nt][mt][q] = 0.f;

#pragma unroll
    for (int nt = 0; nt < 8; nt++) {
        uint32_t b0[4], b1[4];
        int nrow = nt * 8 + g;
#pragma unroll
        for (int kc = 0; kc < 4; kc++) {
            b0[kc] = *reinterpret_cast<const uint32_t*>(&wt[nrow * XS_STRIDE + kc * 16 + 2 * t]);
            b1[kc] = *reinterpret_cast<const uint32_t*>(&wt[nrow * XS_STRIDE + kc * 16 + 8 + 2 * t]);
        }
#pragma unroll
        for (int mt = 0; mt < 2; mt++) {
#pragma unroll
            for (int kc = 0; kc < 4; kc++) {
                asm volatile(
                    "mma.sync.aligned.m16n8k16.row.col.f32.f16.f16.f32 "
                    "{%0,%1,%2,%3}, {%4,%5,%6,%7}, {%8,%9}, {%0,%1,%2,%3};"
                    : "+f"(c[nt][mt][0]), "+f"(c[nt][mt][1]),
                      "+f"(c[nt][mt][2]), "+f"(c[nt][mt][3])
                    : "r"(afr[mt][kc][0]), "r"(afr[mt][kc][1]),
                      "r"(afr[mt][kc][2]), "r"(afr[mt][kc][3]),
                      "r"(b0[kc]), "r"(b1[kc]));
            }
        }
    }
    __syncthreads();   // xs reuse

    // ---- epilogue: frags -> shared (conflict-free) ----
#pragma unroll
    for (int mt = 0; mt < 2; mt++) {
        int rl = wid * 32 + mt * 16 + g;
#pragma unroll
        for (int nt = 0; nt < 8; nt++) {
            int col = nt * 8 + 2 * t;
            *reinterpret_cast<__half2*>(&xs[rl * XS_STRIDE + col]) =
                __floats2half2_rn(c[nt][mt][0], c[nt][mt][1]);
            *reinterpret_cast<__half2*>(&xs[(rl + 8) * XS_STRIDE + col]) =
                __floats2half2_rn(c[nt][mt][2], c[nt][mt][3]);
        }
    }
    __syncthreads();

    // ---- shared -> global, fully coalesced STG.128 ----
    uint4* outp = reinterpret_cast<uint4*>(g_hn) + (size_t)base * 8;
    int limit = (min(256, n - base)) * 8;
#pragma unroll
    for (int ii = 0; ii < 8; ii++) {
        int i = tid + 256 * ii;
        if (i < limit) {
            int r = i >> 3, pc = i & 7;
            outp[i] = reinterpret_cast<uint4*>(&xs[r * XS_STRIDE])[pc];
        }
    }

    // ---- TAIL: fused bucket scatter (layer 0; e2 = E/2 int2 pairs) ----
    // 2x unrolled grid-stride: 8 independent atomics in flight per iter.
    if (layer == 0) {
        int nthreads = gridDim.x * 256;
        int i = base + tid;
        for (; i + nthreads < e2; i += 2 * nthreads) {
            int2 sA = reinterpret_cast<const int2*>(src)[i];
            int2 dA = reinterpret_cast<const int2*>(dst)[i];
            int2 sB = reinterpret_cast<const int2*>(src)[i + nthreads];
            int2 dB = reinterpret_cast<const int2*>(dst)[i + nthreads];
            int dd[4] = {dA.x, dA.y, dB.x, dB.y};
            int ss[4] = {sA.x, sA.y, sB.x, sB.y};
#pragma unroll
            for (int q = 0; q < 4; q++) {
                if ((unsigned)dd[q] >= (unsigned)n || (unsigned)ss[q] >= (unsigned)n) continue;
                int slot = atomicAdd(&g_cnt[dd[q]], 1);
                if (slot < CAP) g_bkt[(size_t)dd[q] * CAP + slot] = ss[q];
            }
        }
        for (; i < e2; i += nthreads) {
            int2 s2 = reinterpret_cast<const int2*>(src)[i];
            int2 d2 = reinterpret_cast<const int2*>(dst)[i];
#pragma unroll
            for (int q = 0; q < 2; q++) {
                int d = q ? d2.y : d2.x;
                int s = q ? s2.y : s2.x;
                if ((unsigned)d >= (unsigned)n || (unsigned)s >= (unsigned)n) continue;
                int slot = atomicAdd(&g_cnt[d], 1);
                if (slot < CAP) g_bkt[(size_t)d * CAP + slot] = s;
            }
        }
    }
}

// ---- dinv materialization: g_dinv = rsqrt(cnt+1)  (cnt zeroed later by agg2)
__global__ void k_dinv(int n) {
    int i = blockIdx.x * blockDim.x + threadIdx.x;
    if (i < n) g_dinv[i] = rsqrtf((float)(g_cnt[i] + 1));
}

// ---- aggregation: out = relu(dinv_d*(dinv_d*hn_d + sum_s dinv_s*hn_s) + b) --
// 8 lanes/node (4 nodes/warp), uint4 row gathers, per-edge dinv broadcast
// loads, fp32 fma accumulate. layer 0 -> fp16 g_h1h; layer 1 -> fp32 d_out
// (and zeroes g_cnt[node] after the warp-converged cnt read).
__global__ void __launch_bounds__(256) k_agg(
    const float* __restrict__ b, float* __restrict__ dout,
    int layer, int n) {
    int tid = blockIdx.x * blockDim.x + threadIdx.x;
    int node = tid >> 3;
    int sub = tid & 7;                 // owns half2[4*sub .. 4*sub+3]
    if (node >= n) return;
    const uint4* hn4 = reinterpret_cast<const uint4*>(g_hn);

    int cnt = g_cnt[node];
    float di = g_dinv[node];
    int len = min(cnt, CAP);
    const int4* bp = reinterpret_cast<const int4*>(g_bkt + (size_t)node * CAP);

    uint4 uself = hn4[(size_t)node * 8 + sub];
    float2 f0 = __half22float2(*reinterpret_cast<__half2*>(&uself.x));
    float2 f1 = __half22float2(*reinterpret_cast<__half2*>(&uself.y));
    float2 f2 = __half22float2(*reinterpret_cast<__half2*>(&uself.z));
    float2 f3 = __half22float2(*reinterpret_cast<__half2*>(&uself.w));
    float2 a0 = {f0.x * di, f0.y * di}, a1 = {f1.x * di, f1.y * di};
    float2 a2 = {f2.x * di, f2.y * di}, a3 = {f3.x * di, f3.y * di};
    float2 c0 = {0.f, 0.f}, c1 = {0.f, 0.f}, c2 = {0.f, 0.f}, c3 = {0.f, 0.f};

#define ACCS(U, DS, X0, X1, X2, X3)                                       \
    {                                                                     \
        float2 h0 = __half22float2(*reinterpret_cast<__half2*>(&(U).x));  \
        float2 h1 = __half22float2(*reinterpret_cast<__half2*>(&(U).y));  \
        float2 h2 = __half22float2(*reinterpret_cast<__half2*>(&(U).z));  \
        float2 h3 = __half22float2(*reinterpret_cast<__half2*>(&(U).w));  \
        X0.x = fmaf(h0.x, DS, X0.x); X0.y = fmaf(h0.y, DS, X0.y);         \
        X1.x = fmaf(h1.x, DS, X1.x); X1.y = fmaf(h1.y, DS, X1.y);         \
        X2.x = fmaf(h2.x, DS, X2.x); X2.y = fmaf(h2.y, DS, X2.y);         \
        X3.x = fmaf(h3.x, DS, X3.x); X3.y = fmaf(h3.y, DS, X3.y);         \
    }

    int p = 0;
    for (; p + 4 <= len; p += 4) {
        int4 e = bp[p >> 2];                      // broadcast across 8 lanes
        float d0 = g_dinv[e.x], d1 = g_dinv[e.y];
        float d2v = g_dinv[e.z], d3v = g_dinv[e.w];
        uint4 u0 = hn4[(size_t)e.x * 8 + sub];
        uint4 u1 = hn4[(size_t)e.y * 8 + sub];
        uint4 u2 = hn4[(size_t)e.z * 8 + sub];
        uint4 u3 = hn4[(size_t)e.w * 8 + sub];
        ACCS(u0, d0, a0, a1, a2, a3)
        ACCS(u1, d1, c0, c1, c2, c3)
        ACCS(u2, d2v, a0, a1, a2, a3)
        ACCS(u3, d3v, c0, c1, c2, c3)
    }
    for (; p < len; p++) {
        int s = g_bkt[(size_t)node * CAP + p];
        float ds = g_dinv[s];
        uint4 u0 = hn4[(size_t)s * 8 + sub];
        ACCS(u0, ds, a0, a1, a2, a3)
    }
#undef ACCS

    if (layer == 1 && sub == 0) g_cnt[node] = 0;   // clean for next replay

    const float4* b4 = reinterpret_cast<const float4*>(b);
    float4 bA = b4[sub * 2], bB = b4[sub * 2 + 1];
    float vA0 = fmaxf((a0.x + c0.x) * di + bA.x, 0.f);
    float vA1 = fmaxf((a0.y + c0.y) * di + bA.y, 0.f);
    float vA2 = fmaxf((a1.x + c1.x) * di + bA.z, 0.f);
    float vA3 = fmaxf((a1.y + c1.y) * di + bA.w, 0.f);
    float vB0 = fmaxf((a2.x + c2.x) * di + bB.x, 0.f);
    float vB1 = fmaxf((a2.y + c2.y) * di + bB.y, 0.f);
    float vB2 = fmaxf((a3.x + c3.x) * di + bB.z, 0.f);
    float vB3 = fmaxf((a3.y + c3.y) * di + bB.w, 0.f);

    if (layer == 0) {
        __half2 h0 = __floats2half2_rn(vA0, vA1);
        __half2 h1 = __floats2half2_rn(vA2, vA3);
        __half2 h2 = __floats2half2_rn(vB0, vB1);
        __half2 h3 = __floats2half2_rn(vB2, vB3);
        uint4 pk;
        pk.x = *reinterpret_cast<unsigned*>(&h0);
        pk.y = *reinterpret_cast<unsigned*>(&h1);
        pk.z = *reinterpret_cast<unsigned*>(&h2);
        pk.w = *reinterpret_cast<unsigned*>(&h3);
        reinterpret_cast<uint4*>(g_h1h + (size_t)node * DD)[sub] = pk;
    } else {
        float4* op = reinterpret_cast<float4*>(dout + (size_t)node * DD + sub * 8);
        op[0] = make_float4(vA0, vA1, vA2, vA3);
        op[1] = make_float4(vB0, vB1, vB2, vB3);
    }
}

// ---------------- launch (ONLY kernel launches — nothing else) ----------------
extern "C" void kernel_launch(void* const* d_in, const int* in_sizes, int n_in,
                              void* d_out, int out_size) {
    const float* emb = (const float*)d_in[0];
    const int*   ei  = (const int*)d_in[1];     // int32 (JAX x64 disabled)
    const float* W1  = (const float*)d_in[2];
    const float* b1  = (const float*)d_in[3];
    const float* W2  = (const float*)d_in[4];
    const float* b2  = (const float*)d_in[5];
    float*       out = (float*)d_out;

    int N = in_sizes[0] / DD;
    int E = in_sizes[1] / 2;
    const int* srcp = ei;       // edge_index[0]
    const int* dstp = ei + E;   // edge_index[1]
    int e2 = E / 2;             // int2 pairs
    int gblocks = (N + 255) / 256;

    // layer 1 GEMM with tail-fused edge scatter
    k_gemm<<<gblocks, 256>>>(emb, W1, srcp, dstp, e2, 0, N);
    k_dinv<<<(N + 255) / 256, 256>>>(N);
    k_agg<<<(N * 8 + 255) / 256, 256>>>(b1, out, 0, N);
    // layer 2  (launch #4 -> profiled: control, expect ~12.6us unchanged)
    k_gemm<<<gblocks, 256>>>(emb, W2, srcp, dstp, 0, 1, N);
    k_agg<<<(N * 8 + 255) / 256, 256>>>(b2, out, 1, N);
}

// round 12
// speedup vs baseline: 1.1003x; 1.1003x over previous
#include <cuda_runtime.h>
#include <cuda_fp16.h>
#include <cstdint>

// Problem constants (fixed by the dataset)
#define NN 100000
#define NE 1600000
#define DD 64
#define CAP 64          // bucket capacity per node (Poisson(16): P(deg>64)~2e-22)

#define XS_STRIDE 72    // halves; 144B rows: 16B-aligned + conflict-free ldmatrix

// ---------------- device scratch (no allocations allowed) ----------------
// g_cnt relies on BSS zero-init; agg layer-2 re-zeroes it (replay invariant).
__device__ __align__(256) int     g_cnt[NN];
__device__ __align__(256) int     g_bkt[(size_t)NN * CAP];   // bucket CSR
__device__ __align__(256) __half2 g_hn[(size_t)NN * 32];     // (x@W)*dinv, fp16
__device__ __align__(256) __half  g_h1h[(size_t)NN * DD];    // layer-1 out, fp16

// ------------- standalone bucket scatter: 4 edges/thread via int4 -----------
__global__ void k_scatter(const int* __restrict__ src,
                          const int* __restrict__ dst, int e4, int n) {
    int i = blockIdx.x * blockDim.x + threadIdx.x;
    if (i >= e4) return;
    int4 s4 = reinterpret_cast<const int4*>(src)[i];
    int4 d4 = reinterpret_cast<const int4*>(dst)[i];
    int dd[4] = {d4.x, d4.y, d4.z, d4.w};
    int ss[4] = {s4.x, s4.y, s4.z, s4.w};
#pragma unroll
    for (int q = 0; q < 4; q++) {
        if ((unsigned)dd[q] >= (unsigned)n || (unsigned)ss[q] >= (unsigned)n) continue;
        int slot = atomicAdd(&g_cnt[dd[q]], 1);
        if (slot < CAP) g_bkt[(size_t)dd[q] * CAP + slot] = ss[q];
    }
}

// -------- GEMM: g_hn[row] = fp16((x@W) * rsqrt(cnt[row]+1)) -----------------
// Runs AFTER scatter -> counts final -> dinv computed inline (no k_dinv).
// Block = 256 threads/8 warps/256 rows. mma.sync.m16n8k16 f32.f16.f16.f32.
// Epilogue: frags -> shared -> fully coalesced STG.128.
__global__ void __launch_bounds__(256) k_gemm(
    const float* __restrict__ emb, const float* __restrict__ W,
    int layer, int n) {
    __shared__ __half xs[256 * XS_STRIDE];       // 36864 B
    __shared__ __half wt[64 * XS_STRIDE];        //  9216 B  (wt[n][k])
    int tid = threadIdx.x;
    int base = blockIdx.x * 256;

    // ---- stage x rows -> fp16 shared ----
    if (layer == 0) {
        int row = base + tid;
        const float4* xr = reinterpret_cast<const float4*>(emb + (size_t)row * DD);
        bool v = row < n;
        __half2* dstp = reinterpret_cast<__half2*>(&xs[tid * XS_STRIDE]);
#pragma unroll
        for (int kk = 0; kk < 16; kk++) {
            float4 q = v ? xr[kk] : make_float4(0.f, 0.f, 0.f, 0.f);
            dstp[kk * 2]     = __floats2half2_rn(q.x, q.y);
            dstp[kk * 2 + 1] = __floats2half2_rn(q.z, q.w);
        }
    } else {
        const uint4* inp = reinterpret_cast<const uint4*>(g_h1h);
        uint4 z = make_uint4(0, 0, 0, 0);
#pragma unroll
        for (int ii = 0; ii < 8; ii++) {
            int i = tid + 256 * ii;
            int r = i >> 3, pc = i & 7;
            int gr = base + r;
            uint4 v = (gr < n) ? inp[(size_t)gr * 8 + pc] : z;
            reinterpret_cast<uint4*>(&xs[r * XS_STRIDE])[pc] = v;
        }
    }
    // ---- stage W -> fp16 transposed shared (wt[n][k]) ----
    {
        const float4* Wp4 = reinterpret_cast<const float4*>(W);
#pragma unroll
        for (int ii = 0; ii < 4; ii++) {
            int i4 = tid + 256 * ii;             // 1024 float4 total
            float4 wv = Wp4[i4];
            int flat = i4 * 4;
            int k = flat >> 6;
            int nn = flat & 63;
            wt[(nn)     * XS_STRIDE + k] = __float2half_rn(wv.x);
            wt[(nn + 1) * XS_STRIDE + k] = __float2half_rn(wv.y);
            wt[(nn + 2) * XS_STRIDE + k] = __float2half_rn(wv.z);
            wt[(nn + 3) * XS_STRIDE + k] = __float2half_rn(wv.w);
        }
    }
    __syncthreads();

    int wid = tid >> 5, lane = tid & 31;
    int g = lane >> 2, t = lane & 3;
    uint32_t xs_u32 = (uint32_t)__cvta_generic_to_shared(xs);

    // A fragments via ldmatrix.x4
    uint32_t afr[2][4][4];
#pragma unroll
    for (int mt = 0; mt < 2; mt++) {
        int rsh = wid * 32 + mt * 16 + (lane & 15);
#pragma unroll
        for (int kc = 0; kc < 4; kc++) {
            uint32_t addr = xs_u32 + rsh * (XS_STRIDE * 2) + kc * 32 + (lane >> 4) * 16;
            asm volatile("ldmatrix.sync.aligned.m8n8.x4.shared.b16 {%0,%1,%2,%3}, [%4];"
                         : "=r"(afr[mt][kc][0]), "=r"(afr[mt][kc][1]),
                           "=r"(afr[mt][kc][2]), "=r"(afr[mt][kc][3])
                         : "r"(addr));
        }
    }

    float c[8][2][4];
#pragma unroll
    for (int nt = 0; nt < 8; nt++)
#pragma unroll
        for (int mt = 0; mt < 2; mt++)
#pragma unroll
            for (int q = 0; q < 4; q++) c[nt][mt][q] = 0.f;

#pragma unroll
    for (int nt = 0; nt < 8; nt++) {
        uint32_t b0[4], b1[4];
        int nrow = nt * 8 + g;
#pragma unroll
        for (int kc = 0; kc < 4; kc++) {
            b0[kc] = *reinterpret_cast<const uint32_t*>(&wt[nrow * XS_STRIDE + kc * 16 + 2 * t]);
            b1[kc] = *reinterpret_cast<const uint32_t*>(&wt[nrow * XS_STRIDE + kc * 16 + 8 + 2 * t]);
        }
#pragma unroll
        for (int mt = 0; mt < 2; mt++) {
#pragma unroll
            for (int kc = 0; kc < 4; kc++) {
                asm volatile(
                    "mma.sync.aligned.m16n8k16.row.col.f32.f16.f16.f32 "
                    "{%0,%1,%2,%3}, {%4,%5,%6,%7}, {%8,%9}, {%0,%1,%2,%3};"
                    : "+f"(c[nt][mt][0]), "+f"(c[nt][mt][1]),
                      "+f"(c[nt][mt][2]), "+f"(c[nt][mt][3])
                    : "r"(afr[mt][kc][0]), "r"(afr[mt][kc][1]),
                      "r"(afr[mt][kc][2]), "r"(afr[mt][kc][3]),
                      "r"(b0[kc]), "r"(b1[kc]));
            }
        }
    }
    __syncthreads();   // xs reuse

    // ---- epilogue: scale by dinv, frags -> shared (conflict-free) ----
#pragma unroll
    for (int mt = 0; mt < 2; mt++) {
        int rl = wid * 32 + mt * 16 + g;
        int r0 = base + rl, r1 = r0 + 8;
        float di0 = (r0 < n) ? rsqrtf((float)(g_cnt[r0] + 1)) : 0.f;
        float di1 = (r1 < n) ? rsqrtf((float)(g_cnt[r1] + 1)) : 0.f;
#pragma unroll
        for (int nt = 0; nt < 8; nt++) {
            int col = nt * 8 + 2 * t;
            *reinterpret_cast<__half2*>(&xs[rl * XS_STRIDE + col]) =
                __floats2half2_rn(c[nt][mt][0] * di0, c[nt][mt][1] * di0);
            *reinterpret_cast<__half2*>(&xs[(rl + 8) * XS_STRIDE + col]) =
                __floats2half2_rn(c[nt][mt][2] * di1, c[nt][mt][3] * di1);
        }
    }
    __syncthreads();

    // ---- shared -> global, fully coalesced STG.128 ----
    uint4* outp = reinterpret_cast<uint4*>(g_hn) + (size_t)base * 8;
    int limit = (min(256, n - base)) * 8;
#pragma unroll
    for (int ii = 0; ii < 8; ii++) {
        int i = tid + 256 * ii;
        if (i < limit) {
            int r = i >> 3, pc = i & 7;
            outp[i] = reinterpret_cast<uint4*>(&xs[r * XS_STRIDE])[pc];
        }
    }
}

// ---- aggregation: out = relu(dinv_d*(hn_d + sum_s hn_s) + b) ---------------
// hn pre-scaled by dinv[src] -> inner loop is pure adds, no dinv gathers.
// 8 lanes/node (4 nodes/warp), uint4 row gathers, bucket indices as int4.
// layer 0 -> fp16 g_h1h; layer 1 -> fp32 d_out + zeroes g_cnt (replay).
__global__ void __launch_bounds__(256) k_agg(
    const float* __restrict__ b, float* __restrict__ dout,
    int layer, int n) {
    int tid = blockIdx.x * blockDim.x + threadIdx.x;
    int node = tid >> 3;
    int sub = tid & 7;                 // owns half2[4*sub .. 4*sub+3]
    if (node >= n) return;
    const uint4* hn4 = reinterpret_cast<const uint4*>(g_hn);

    int cnt = g_cnt[node];
    float di = rsqrtf((float)(cnt + 1));
    int len = min(cnt, CAP);
    const int4* bp = reinterpret_cast<const int4*>(g_bkt + (size_t)node * CAP);

    uint4 uself = hn4[(size_t)node * 8 + sub];
    float2 a0 = __half22float2(*reinterpret_cast<__half2*>(&uself.x));
    float2 a1 = __half22float2(*reinterpret_cast<__half2*>(&uself.y));
    float2 a2 = __half22float2(*reinterpret_cast<__half2*>(&uself.z));
    float2 a3 = __half22float2(*reinterpret_cast<__half2*>(&uself.w));
    float2 c0 = {0.f, 0.f}, c1 = {0.f, 0.f}, c2 = {0.f, 0.f}, c3 = {0.f, 0.f};

#define ACC_U4(U, X0, X1, X2, X3)                                         \
    {                                                                     \
        float2 f0 = __half22float2(*reinterpret_cast<__half2*>(&(U).x));  \
        float2 f1 = __half22float2(*reinterpret_cast<__half2*>(&(U).y));  \
        float2 f2 = __half22float2(*reinterpret_cast<__half2*>(&(U).z));  \
        float2 f3 = __half22float2(*reinterpret_cast<__half2*>(&(U).w));  \
        X0.x += f0.x; X0.y += f0.y; X1.x += f1.x; X1.y += f1.y;           \
        X2.x += f2.x; X2.y += f2.y; X3.x += f3.x; X3.y += f3.y;           \
    }

    int p = 0;
    for (; p + 4 <= len; p += 4) {
        int4 e = bp[p >> 2];                      // broadcast across 8 lanes
        uint4 u0 = hn4[(size_t)e.x * 8 + sub];
        uint4 u1 = hn4[(size_t)e.y * 8 + sub];
        uint4 u2 = hn4[(size_t)e.z * 8 + sub];
        uint4 u3 = hn4[(size_t)e.w * 8 + sub];
        ACC_U4(u0, a0, a1, a2, a3)
        ACC_U4(u1, c0, c1, c2, c3)
        ACC_U4(u2, a0, a1, a2, a3)
        ACC_U4(u3, c0, c1, c2, c3)
    }
    for (; p < len; p++) {
        int s = g_bkt[(size_t)node * CAP + p];
        uint4 u0 = hn4[(size_t)s * 8 + sub];
        ACC_U4(u0, a0, a1, a2, a3)
    }
#undef ACC_U4

    if (layer == 1 && sub == 0) g_cnt[node] = 0;   // clean for next replay

    const float4* b4 = reinterpret_cast<const float4*>(b);
    float4 bA = b4[sub * 2], bB = b4[sub * 2 + 1];
    float vA0 = fmaxf((a0.x + c0.x) * di + bA.x, 0.f);
    float vA1 = fmaxf((a0.y + c0.y) * di + bA.y, 0.f);
    float vA2 = fmaxf((a1.x + c1.x) * di + bA.z, 0.f);
    float vA3 = fmaxf((a1.y + c1.y) * di + bA.w, 0.f);
    float vB0 = fmaxf((a2.x + c2.x) * di + bB.x, 0.f);
    float vB1 = fmaxf((a2.y + c2.y) * di + bB.y, 0.f);
    float vB2 = fmaxf((a3.x + c3.x) * di + bB.z, 0.f);
    float vB3 = fmaxf((a3.y + c3.y) * di + bB.w, 0.f);

    if (layer == 0) {
        __half2 h0 = __floats2half2_rn(vA0, vA1);
        __half2 h1 = __floats2half2_rn(vA2, vA3);
        __half2 h2 = __floats2half2_rn(vB0, vB1);
        __half2 h3 = __floats2half2_rn(vB2, vB3);
        uint4 pk;
        pk.x = *reinterpret_cast<unsigned*>(&h0);
        pk.y = *reinterpret_cast<unsigned*>(&h1);
        pk.z = *reinterpret_cast<unsigned*>(&h2);
        pk.w = *reinterpret_cast<unsigned*>(&h3);
        reinterpret_cast<uint4*>(g_h1h + (size_t)node * DD)[sub] = pk;
    } else {
        float4* op = reinterpret_cast<float4*>(dout + (size_t)node * DD + sub * 8);
        op[0] = make_float4(vA0, vA1, vA2, vA3);
        op[1] = make_float4(vB0, vB1, vB2, vB3);
    }
}

// ---------------- launch (ONLY kernel launches — nothing else) ----------------
extern "C" void kernel_launch(void* const* d_in, const int* in_sizes, int n_in,
                              void* d_out, int out_size) {
    const float* emb = (const float*)d_in[0];
    const int*   ei  = (const int*)d_in[1];     // int32 (JAX x64 disabled)
    const float* W1  = (const float*)d_in[2];
    const float* b1  = (const float*)d_in[3];
    const float* W2  = (const float*)d_in[4];
    const float* b2  = (const float*)d_in[5];
    float*       out = (float*)d_out;

    int N = in_sizes[0] / DD;
    int E = in_sizes[1] / 2;
    const int* srcp = ei;       // edge_index[0]
    const int* dstp = ei + E;   // edge_index[1]
    int e4 = E / 4;             // int4 quads
    int gblocks = (N + 255) / 256;

    // preprocessing: single-pass bucket scatter (counts final before gemm1)
    k_scatter<<<(e4 + 255) / 256, 256>>>(srcp, dstp, e4, N);

    // layer 1
    k_gemm<<<gblocks, 256>>>(emb, W1, 0, N);
    k_agg<<<(N * 8 + 255) / 256, 256>>>(b1, out, 0, N);
    // layer 2  (launch #4 -> profiled: control, expect ~12.5us)
    k_gemm<<<gblocks, 256>>>(emb, W2, 1, N);
    k_agg<<<(N * 8 + 255) / 256, 256>>>(b2, out, 1, N);
}